// round 15
// baseline (speedup 1.0000x reference)
#include <cuda_runtime.h>
#include <cuda_fp16.h>
#include <cstdint>

#define BB 2
#define HH 16
#define SS 2048
#define DH 128
#define BM 128
#define BN 128
#define NITER 16
#define NSTILE 16
#define NTHREADS 512

// smem byte layout (r11, mask region now fp16 with 272B row stride)
#define QSB 272
#define KVST 34816
#define SM_Q 0
#define SM_K 34816
#define SM_V 104448
#define SM_M 139264          // 128 rows x 272B fp16 = 34816 used
#define SM_R 208896
#define SM_OST SM_K
#define SMEM_BYTES 209920

__device__ __half KH[BB * HH * SS * DH];
__device__ __half VH[BB * HH * SS * DH];

__device__ __forceinline__ uint32_t smem_u32(const void* p) {
    uint32_t a;
    asm("{ .reg .u64 t; cvta.to.shared.u64 t, %1; cvt.u32.u64 %0, t; }" : "=r"(a) : "l"(p));
    return a;
}
__device__ __forceinline__ void ldsm_x4(uint32_t& r0, uint32_t& r1, uint32_t& r2, uint32_t& r3, uint32_t a) {
    asm volatile("ldmatrix.sync.aligned.m8n8.x4.shared.b16 {%0,%1,%2,%3}, [%4];"
                 : "=r"(r0), "=r"(r1), "=r"(r2), "=r"(r3) : "r"(a));
}
__device__ __forceinline__ void ldsm_x4t(uint32_t& r0, uint32_t& r1, uint32_t& r2, uint32_t& r3, uint32_t a) {
    asm volatile("ldmatrix.sync.aligned.m8n8.x4.trans.shared.b16 {%0,%1,%2,%3}, [%4];"
                 : "=r"(r0), "=r"(r1), "=r"(r2), "=r"(r3) : "r"(a));
}
__device__ __forceinline__ void mma16816(float* c, uint32_t a0, uint32_t a1, uint32_t a2, uint32_t a3,
                                         uint32_t b0, uint32_t b1) {
    asm volatile(
        "mma.sync.aligned.m16n8k16.row.col.f32.f16.f16.f32 "
        "{%0,%1,%2,%3}, {%4,%5,%6,%7}, {%8,%9}, {%0,%1,%2,%3};"
        : "+f"(c[0]), "+f"(c[1]), "+f"(c[2]), "+f"(c[3])
        : "r"(a0), "r"(a1), "r"(a2), "r"(a3), "r"(b0), "r"(b1));
}
__device__ __forceinline__ void cpa16(uint32_t dst, const void* src) {
    asm volatile("cp.async.cg.shared.global [%0], [%1], 16;" :: "r"(dst), "l"(src) : "memory");
}
#define CPA_COMMIT asm volatile("cp.async.commit_group;" ::: "memory")
#define CPA_WAIT(n) asm volatile("cp.async.wait_group %0;" :: "n"(n) : "memory")
#define GBAR asm volatile("bar.sync %0, 256;" :: "r"(wn + 1) : "memory")

__device__ __forceinline__ uint2 f4h4(float4 v) {
    __half2 a = __floats2half2_rn(v.x, v.y);
    __half2 b = __floats2half2_rn(v.z, v.w);
    uint2 w;
    w.x = *(uint32_t*)&a;
    w.y = *(uint32_t*)&b;
    return w;
}
__device__ __forceinline__ uint32_t packh2(float a, float b) {
    __half2 h = __floats2half2_rn(a, b);
    return *(uint32_t*)&h;
}

__global__ __launch_bounds__(512, 2)
void conv_kv(const float* __restrict__ k, const float* __restrict__ v) {
    int i = blockIdx.x * blockDim.x + threadIdx.x;
    ((uint2*)KH)[i] = f4h4(((const float4*)k)[i]);
    ((uint2*)VH)[i] = f4h4(((const float4*)v)[i]);
}

__global__ __launch_bounds__(NTHREADS, 1)
void retatt_k15(const float* __restrict__ q, const float* __restrict__ mask,
                float* __restrict__ o)
{
    extern __shared__ char smem[];
    const uint32_t sbase = smem_u32(smem);
    const int tid = threadIdx.x;
    const int wid = tid >> 5;
    const int lane = tid & 31;
    const int g = lane >> 2;
    const int t = lane & 3;
    const int wm = wid >> 1;            // r8/r11 mapping
    const int wn = wid & 1;
    const int m_base = wm * 16;
    const int n_base = wn * 64;
    const int lrow = lane & 15;
    const int lchunk = (lane >> 4) * 16;
    const int gt = wm * 32 + lane;

    const int bid = blockIdx.x;
    const int b  = bid & 1;
    const int r_ = bid >> 1;
    const int h  = r_ / NSTILE;
    const int st = r_ % NSTILE;
    const int s0 = st * BM;

    const float* qbase = q + ((size_t)(b * HH + h) * SS + s0) * DH;
    const __half* khb = KH + ((size_t)(b * HH + h) * SS) * DH;
    const __half* vhb = VH + ((size_t)(b * HH + h) * SS) * DH;
    const float* mbase = mask + ((size_t)h * SS + s0) * SS;

    float4 mreg[8];   // mask staging: live only from post-GEMM2 LDG to next-iter STS

    // ---- prologue: Q fp16; K0 via cp.async; mask(0) LDG into staging regs ----
    {
        const float4* gq = (const float4*)qbase;
        #pragma unroll
        for (int i = 0; i < 8; ++i) {
            int f = tid + i * NTHREADS;
            int row = f >> 5, d = (f & 31) << 2;
            *(uint2*)(smem + SM_Q + row * QSB + d * 2) = f4h4(gq[f]);
        }
        #pragma unroll
        for (int i = 0; i < 4; ++i) {
            int f = gt + i * 256;
            int lr = f >> 4, c16 = f & 15;
            cpa16(sbase + SM_K + (n_base + lr) * QSB + c16 * 16,
                  khb + (size_t)(n_base + lr) * DH + c16 * 8);
        }
        CPA_COMMIT;                     // group {K0}
        #pragma unroll
        for (int i = 0; i < 8; ++i) {   // mask(0) rows x group's 64-col half
            int f = gt + i * 256;
            int row = f >> 4, c4 = (f & 15) << 2;
            mreg[i] = *(const float4*)(mbase + (size_t)row * SS + n_base + c4);
        }
        __syncthreads();
    }

    float acc2[16][4];
    #pragma unroll
    for (int nt = 0; nt < 16; ++nt)
        #pragma unroll
        for (int i = 0; i < 4; ++i) acc2[nt][i] = 0.f;
    float rsum[2] = {0.f, 0.f};

    const uint32_t qa = sbase + SM_Q + (uint32_t)(m_base + lrow) * QSB + lchunk;
    const uint32_t sV = sbase + SM_V;

    #pragma unroll 1
    for (int it = 0; it < NITER; ++it) {
        const uint32_t sKb = sbase + SM_K + (it & 1) * KVST;

        // ---- STS mask(it) from staging regs (fp16); safe: end-GBAR(it-1) passed ----
        #pragma unroll
        for (int i = 0; i < 8; ++i) {
            int f = gt + i * 256;
            int row = f >> 4, c4 = (f & 15) << 2;
            *(uint2*)(smem + SM_M + row * QSB + (n_base + c4) * 2) = f4h4(mreg[i]);
        }

        // ---- cp.async: group {V(it)}, then group {K(it+1)} ----
        {
            #pragma unroll
            for (int i = 0; i < 4; ++i) {
                int f = gt + i * 256;
                int lr = f >> 4, c16 = f & 15;
                cpa16(sV + (n_base + lr) * QSB + c16 * 16,
                      vhb + (size_t)(it * BN + n_base + lr) * DH + c16 * 8);
            }
            CPA_COMMIT;                 // group {V}
            if (it + 1 < NITER) {
                const uint32_t kd = sbase + SM_K + ((it + 1) & 1) * KVST;
                #pragma unroll
                for (int i = 0; i < 4; ++i) {
                    int f = gt + i * 256;
                    int lr = f >> 4, c16 = f & 15;
                    cpa16(kd + (n_base + lr) * QSB + c16 * 16,
                          khb + (size_t)((it + 1) * BN + n_base + lr) * DH + c16 * 8);
                }
            }
            CPA_COMMIT;                 // group {K(it+1)} (possibly empty)
        }

        CPA_WAIT(2);                    // K(it) complete
        if (it == 0) GBAR;              // K0 cross-warp visibility

        // ---- GEMM1: S[16 x 64] per warp = Q @ K_slice^T (r11 form) ----
        float acc1[8][4];
        #pragma unroll
        for (int nt = 0; nt < 8; ++nt)
            #pragma unroll
            for (int i = 0; i < 4; ++i) acc1[nt][i] = 0.f;

        const uint32_t kb0 = sKb + (uint32_t)(n_base + lrow) * QSB + lchunk;
        #pragma unroll
        for (int kk = 0; kk < 8; ++kk) {
            uint32_t a0, a1, a2, a3;
            ldsm_x4(a0, a1, a2, a3, qa + kk * 32);
            #pragma unroll
            for (int j = 0; j < 4; ++j) {
                uint32_t b0, b1, b2, b3;
                ldsm_x4(b0, b1, b2, b3, kb0 + j * 16 * QSB + kk * 32);
                mma16816(acc1[2 * j],     a0, a1, a2, a3, b0, b2);
                mma16816(acc1[2 * j + 1], a0, a1, a2, a3, b1, b3);
            }
        }

        CPA_WAIT(1);                    // V(it) complete
        GBAR;                           // V + all warps' mask STS visible (bar drains STS)

        // ---- fused epilogue + GEMM2 per k-block (mask fp16 reads) ----
        const uint32_t moff = SM_M + (uint32_t)(m_base + g) * QSB
                            + (uint32_t)(n_base + 2 * t) * 2;
        #pragma unroll
        for (int kb = 0; kb < 4; ++kb) {
            const uint32_t vrow = sV + (uint32_t)(n_base + kb * 16 + lrow) * QSB + lchunk;

            uint32_t v00, v01, v02, v03, v10, v11, v12, v13;
            ldsm_x4t(v00, v01, v02, v03, vrow);
            ldsm_x4t(v10, v11, v12, v13, vrow + 32);

            uint32_t A0, A1, A2, A3;
            {
                const int nt0 = 2 * kb;
                float2 m0 = __half22float2(*(const __half2*)(smem + moff + nt0 * 16));
                float2 m1 = __half22float2(*(const __half2*)(smem + moff + 8 * QSB + nt0 * 16));
                float p0 = acc1[nt0][0] * m0.x;
                float p1 = acc1[nt0][1] * m0.y;
                float p2 = acc1[nt0][2] * m1.x;
                float p3 = acc1[nt0][3] * m1.y;
                rsum[0] += fabsf(p0) + fabsf(p1);
                rsum[1] += fabsf(p2) + fabsf(p3);
                A0 = packh2(p0, p1);
                A1 = packh2(p2, p3);

                const int nt1 = nt0 + 1;
                float2 m2 = __half22float2(*(const __half2*)(smem + moff + nt1 * 16));
                float2 m3 = __half22float2(*(const __half2*)(smem + moff + 8 * QSB + nt1 * 16));
                float q0 = acc1[nt1][0] * m2.x;
                float q1 = acc1[nt1][1] * m2.y;
                float q2 = acc1[nt1][2] * m3.x;
                float q3 = acc1[nt1][3] * m3.y;
                rsum[0] += fabsf(q0) + fabsf(q1);
                rsum[1] += fabsf(q2) + fabsf(q3);
                A2 = packh2(q0, q1);
                A3 = packh2(q2, q3);
            }

            mma16816(acc2[0], A0, A1, A2, A3, v00, v01);
            mma16816(acc2[1], A0, A1, A2, A3, v02, v03);
            mma16816(acc2[2], A0, A1, A2, A3, v10, v11);
            mma16816(acc2[3], A0, A1, A2, A3, v12, v13);

            #pragma unroll
            for (int dc = 2; dc < 8; ++dc) {
                uint32_t w0, w1, w2, w3;
                ldsm_x4t(w0, w1, w2, w3, vrow + dc * 32);
                mma16816(acc2[2 * dc],     A0, A1, A2, A3, w0, w1);
                mma16816(acc2[2 * dc + 1], A0, A1, A2, A3, w2, w3);
            }
        }

        // ---- LDG mask(it+1) into staging (acc1 dead here -> reg peak safe) ----
        if (it + 1 < NITER) {
            #pragma unroll
            for (int i = 0; i < 8; ++i) {
                int f = gt + i * 256;
                int row = f >> 4, c4 = (f & 15) << 2;
                mreg[i] = *(const float4*)(mbase + (size_t)row * SS
                                           + (it + 1) * BN + n_base + c4);
            }
        }

        GBAR;                           // group done with V(it)/mask(it)
    }

    __syncthreads();

    // ---- r reduction ----
    float* sR = (float*)(smem + SM_R);
    #pragma unroll
    for (int half = 0; half < 2; ++half) {
        float vv = rsum[half];
        vv += __shfl_xor_sync(0xffffffffu, vv, 1);
        vv += __shfl_xor_sync(0xffffffffu, vv, 2);
        if (t == 0) sR[wn * BM + m_base + half * 8 + g] = vv;
    }

    // ---- O split-k reduction ----
    float* ost = (float*)(smem + SM_OST);
    if (wn == 0) {
        #pragma unroll
        for (int nt = 0; nt < 16; ++nt) {
            const int row0 = m_base + g;
            const int cb = nt * 8 + 2 * t;
            *(float2*)&ost[row0 * 136 + cb] = make_float2(acc2[nt][0], acc2[nt][1]);
            *(float2*)&ost[(row0 + 8) * 136 + cb] = make_float2(acc2[nt][2], acc2[nt][3]);
        }
    }
    __syncthreads();

    if (wn == 1) {
        float* ob = o + ((size_t)(b * HH + h) * SS + s0) * DH;
        const int row0 = m_base + g;
        const int row1 = row0 + 8;
        const float inv0 = 1.0f / fmaxf(sR[row0] + sR[BM + row0], 1.0f);
        const float inv1 = 1.0f / fmaxf(sR[row1] + sR[BM + row1], 1.0f);
        #pragma unroll
        for (int nt = 0; nt < 16; ++nt) {
            const int cb = nt * 8 + 2 * t;
            float2 s0v = *(const float2*)&ost[row0 * 136 + cb];
            float2 s1v = *(const float2*)&ost[row1 * 136 + cb];
            *(float2*)&ob[(size_t)row0 * DH + cb] =
                make_float2((s0v.x + acc2[nt][0]) * inv0, (s0v.y + acc2[nt][1]) * inv0);
            *(float2*)&ob[(size_t)row1 * DH + cb] =
                make_float2((s1v.x + acc2[nt][2]) * inv1, (s1v.y + acc2[nt][3]) * inv1);
        }
    }
}

extern "C" void kernel_launch(void* const* d_in, const int* in_sizes, int n_in,
                              void* d_out, int out_size) {
    const float* q = (const float*)d_in[0];
    const float* k = (const float*)d_in[1];
    const float* v = (const float*)d_in[2];
    const float* m = (const float*)d_in[3];
    float* o = (float*)d_out;
    conv_kv<<<(BB * HH * SS * DH / 4) / 512, 512>>>(k, v);
    cudaFuncSetAttribute(retatt_k15,
                         cudaFuncAttributeMaxDynamicSharedMemorySize, SMEM_BYTES);
    retatt_k15<<<BB * HH * NSTILE, NTHREADS, SMEM_BYTES>>>(q, m, o);
}

// round 16
// speedup vs baseline: 1.2166x; 1.2166x over previous
#include <cuda_runtime.h>
#include <cuda_fp16.h>
#include <cstdint>

#define BB 2
#define HH 16
#define SS 2048
#define DH 128
#define BM 128
#define BN 128
#define NITER 16
#define NSTILE 16
#define NTHREADS 512

// smem byte layout (r11; mask region now fp16, 272B row stride)
#define QSB 272
#define KVST 34816
#define SM_Q 0
#define SM_K 34816
#define SM_V 104448
#define SM_M 139264          // 128 rows x 272B fp16 = 34816 used
#define SM_R 208896
#define SM_OST SM_K
#define SMEM_BYTES 209920

__device__ __half KH[BB * HH * SS * DH];
__device__ __half VH[BB * HH * SS * DH];

__device__ __forceinline__ uint32_t smem_u32(const void* p) {
    uint32_t a;
    asm("{ .reg .u64 t; cvta.to.shared.u64 t, %1; cvt.u32.u64 %0, t; }" : "=r"(a) : "l"(p));
    return a;
}
__device__ __forceinline__ void ldsm_x4(uint32_t& r0, uint32_t& r1, uint32_t& r2, uint32_t& r3, uint32_t a) {
    asm volatile("ldmatrix.sync.aligned.m8n8.x4.shared.b16 {%0,%1,%2,%3}, [%4];"
                 : "=r"(r0), "=r"(r1), "=r"(r2), "=r"(r3) : "r"(a));
}
__device__ __forceinline__ void ldsm_x4t(uint32_t& r0, uint32_t& r1, uint32_t& r2, uint32_t& r3, uint32_t a) {
    asm volatile("ldmatrix.sync.aligned.m8n8.x4.trans.shared.b16 {%0,%1,%2,%3}, [%4];"
                 : "=r"(r0), "=r"(r1), "=r"(r2), "=r"(r3) : "r"(a));
}
__device__ __forceinline__ void mma16816(float* c, uint32_t a0, uint32_t a1, uint32_t a2, uint32_t a3,
                                         uint32_t b0, uint32_t b1) {
    asm volatile(
        "mma.sync.aligned.m16n8k16.row.col.f32.f16.f16.f32 "
        "{%0,%1,%2,%3}, {%4,%5,%6,%7}, {%8,%9}, {%0,%1,%2,%3};"
        : "+f"(c[0]), "+f"(c[1]), "+f"(c[2]), "+f"(c[3])
        : "r"(a0), "r"(a1), "r"(a2), "r"(a3), "r"(b0), "r"(b1));
}
__device__ __forceinline__ void cpa16(uint32_t dst, const void* src) {
    asm volatile("cp.async.cg.shared.global [%0], [%1], 16;" :: "r"(dst), "l"(src) : "memory");
}
__device__ __forceinline__ void sts8(uint32_t a, uint2 w) {
    asm volatile("st.shared.v2.b32 [%0], {%1, %2};" :: "r"(a), "r"(w.x), "r"(w.y) : "memory");
}
#define CPA_COMMIT asm volatile("cp.async.commit_group;" ::: "memory")
#define CPA_WAIT(n) asm volatile("cp.async.wait_group %0;" :: "n"(n) : "memory")
#define GBAR asm volatile("bar.sync %0, 256;" :: "r"(wn + 1) : "memory")

__device__ __forceinline__ uint2 f4h4(float4 v) {
    __half2 a = __floats2half2_rn(v.x, v.y);
    __half2 b = __floats2half2_rn(v.z, v.w);
    uint2 w;
    w.x = *(uint32_t*)&a;
    w.y = *(uint32_t*)&b;
    return w;
}
__device__ __forceinline__ uint32_t packh2(float a, float b) {
    __half2 h = __floats2half2_rn(a, b);
    return *(uint32_t*)&h;
}

__global__ __launch_bounds__(512, 2)
void conv_kv(const float* __restrict__ k, const float* __restrict__ v) {
    int i = blockIdx.x * blockDim.x + threadIdx.x;
    ((uint2*)KH)[i] = f4h4(((const float4*)k)[i]);
    ((uint2*)VH)[i] = f4h4(((const float4*)v)[i]);
}

__global__ __launch_bounds__(NTHREADS, 1)
void retatt_k16(const float* __restrict__ q, const float* __restrict__ mask,
                float* __restrict__ o)
{
    extern __shared__ char smem[];
    const uint32_t sbase = smem_u32(smem);
    const int tid = threadIdx.x;
    const int wid = tid >> 5;
    const int lane = tid & 31;
    const int g = lane >> 2;
    const int t = lane & 3;
    const int wm = wid >> 1;            // r8/r11 mapping
    const int wn = wid & 1;
    const int m_base = wm * 16;
    const int n_base = wn * 64;
    const int lrow = lane & 15;
    const int lchunk = (lane >> 4) * 16;
    const int gt = wm * 32 + lane;

    const int bid = blockIdx.x;
    const int b  = bid & 1;
    const int r_ = bid >> 1;
    const int h  = r_ / NSTILE;
    const int st = r_ % NSTILE;
    const int s0 = st * BM;

    const float* qbase = q + ((size_t)(b * HH + h) * SS + s0) * DH;
    const __half* khb = KH + ((size_t)(b * HH + h) * SS) * DH;
    const __half* vhb = VH + ((size_t)(b * HH + h) * SS) * DH;
    const float* mbase = mask + ((size_t)h * SS + s0) * SS;

    // per-thread mask staging coordinates (8 chunks: rows gt>>4 + 16i, cols c4)
    const int mrow = gt >> 4;
    const int mc4 = (gt & 15) << 2;

    // ---- prologue: Q fp16; K0 group-half via cp.async ----
    {
        const float4* gq = (const float4*)qbase;
        #pragma unroll
        for (int i = 0; i < 8; ++i) {
            int f = tid + i * NTHREADS;
            int row = f >> 5, d = (f & 31) << 2;
            *(uint2*)(smem + SM_Q + row * QSB + d * 2) = f4h4(gq[f]);
        }
        #pragma unroll
        for (int i = 0; i < 4; ++i) {
            int f = gt + i * 256;
            int lr = f >> 4, c16 = f & 15;
            cpa16(sbase + SM_K + (n_base + lr) * QSB + c16 * 16,
                  khb + (size_t)(n_base + lr) * DH + c16 * 8);
        }
        CPA_COMMIT;                     // group {K0}
        __syncthreads();
    }

    float acc2[16][4];
    #pragma unroll
    for (int nt = 0; nt < 16; ++nt)
        #pragma unroll
        for (int i = 0; i < 4; ++i) acc2[nt][i] = 0.f;
    float rsum[2] = {0.f, 0.f};

    const uint32_t qa = sbase + SM_Q + (uint32_t)(m_base + lrow) * QSB + lchunk;
    const uint32_t sV = sbase + SM_V;

    #pragma unroll 1
    for (int it = 0; it < NITER; ++it) {
        const uint32_t sKb = sbase + SM_K + (it & 1) * KVST;

        // ---- mask(it): LDG burst (issued first to hide latency) ----
        // Staging lifetime is ONLY this block — dead before GEMM1 (acc1 window).
        {
            float4 mreg[8];
            const float* mp = mbase + it * BN + n_base + mc4;
            #pragma unroll
            for (int i = 0; i < 8; ++i)
                mreg[i] = *(const float4*)(mp + (size_t)(mrow + 16 * i) * SS);

            // ---- cp.async: group {V(it)}, then group {K(it+1)} (independent) ----
            #pragma unroll
            for (int i = 0; i < 4; ++i) {
                int f = gt + i * 256;
                int lr = f >> 4, c16 = f & 15;
                cpa16(sV + (n_base + lr) * QSB + c16 * 16,
                      vhb + (size_t)(it * BN + n_base + lr) * DH + c16 * 8);
            }
            CPA_COMMIT;                 // group {V}
            if (it + 1 < NITER) {
                const uint32_t kd = sbase + SM_K + ((it + 1) & 1) * KVST;
                #pragma unroll
                for (int i = 0; i < 4; ++i) {
                    int f = gt + i * 256;
                    int lr = f >> 4, c16 = f & 15;
                    cpa16(kd + (n_base + lr) * QSB + c16 * 16,
                          khb + (size_t)((it + 1) * BN + n_base + lr) * DH + c16 * 8);
                }
            }
            CPA_COMMIT;                 // group {K(it+1)} (possibly empty)

            // ---- cvt + STS fp16 (volatile asm pins placement before GEMM1) ----
            #pragma unroll
            for (int i = 0; i < 8; ++i) {
                uint32_t dst = sbase + SM_M + (uint32_t)(mrow + 16 * i) * QSB
                             + (uint32_t)(n_base + mc4) * 2;
                sts8(dst, f4h4(mreg[i]));
            }
        }

        CPA_WAIT(2);                    // K(it) complete
        if (it == 0) GBAR;              // K0 cross-warp visibility

        // ---- GEMM1: S[16 x 64] per warp = Q @ K_slice^T (r11 form) ----
        float acc1[8][4];
        #pragma unroll
        for (int nt = 0; nt < 8; ++nt)
            #pragma unroll
            for (int i = 0; i < 4; ++i) acc1[nt][i] = 0.f;

        const uint32_t kb0 = sKb + (uint32_t)(n_base + lrow) * QSB + lchunk;
        #pragma unroll
        for (int kk = 0; kk < 8; ++kk) {
            uint32_t a0, a1, a2, a3;
            ldsm_x4(a0, a1, a2, a3, qa + kk * 32);
            #pragma unroll
            for (int j = 0; j < 4; ++j) {
                uint32_t b0, b1, b2, b3;
                ldsm_x4(b0, b1, b2, b3, kb0 + j * 16 * QSB + kk * 32);
                mma16816(acc1[2 * j],     a0, a1, a2, a3, b0, b2);
                mma16816(acc1[2 * j + 1], a0, a1, a2, a3, b1, b3);
            }
        }

        CPA_WAIT(1);                    // V(it) complete
        GBAR;                           // V visible + all warps' mask STS drained

        // ---- fused epilogue + GEMM2 per k-block (mask fp16 reads, r11 flow) ----
        const uint32_t moff = SM_M + (uint32_t)(m_base + g) * QSB
                            + (uint32_t)(n_base + 2 * t) * 2;
        #pragma unroll
        for (int kb = 0; kb < 4; ++kb) {
            const uint32_t vrow = sV + (uint32_t)(n_base + kb * 16 + lrow) * QSB + lchunk;

            uint32_t v00, v01, v02, v03, v10, v11, v12, v13;
            ldsm_x4t(v00, v01, v02, v03, vrow);
            ldsm_x4t(v10, v11, v12, v13, vrow + 32);

            uint32_t A0, A1, A2, A3;
            {
                const int nt0 = 2 * kb;
                float2 m0 = __half22float2(*(const __half2*)(smem + moff + nt0 * 16));
                float2 m1 = __half22float2(*(const __half2*)(smem + moff + 8 * QSB + nt0 * 16));
                float p0 = acc1[nt0][0] * m0.x;
                float p1 = acc1[nt0][1] * m0.y;
                float p2 = acc1[nt0][2] * m1.x;
                float p3 = acc1[nt0][3] * m1.y;
                rsum[0] += fabsf(p0) + fabsf(p1);
                rsum[1] += fabsf(p2) + fabsf(p3);
                A0 = packh2(p0, p1);
                A1 = packh2(p2, p3);

                const int nt1 = nt0 + 1;
                float2 m2 = __half22float2(*(const __half2*)(smem + moff + nt1 * 16));
                float2 m3 = __half22float2(*(const __half2*)(smem + moff + 8 * QSB + nt1 * 16));
                float q0 = acc1[nt1][0] * m2.x;
                float q1 = acc1[nt1][1] * m2.y;
                float q2 = acc1[nt1][2] * m3.x;
                float q3 = acc1[nt1][3] * m3.y;
                rsum[0] += fabsf(q0) + fabsf(q1);
                rsum[1] += fabsf(q2) + fabsf(q3);
                A2 = packh2(q0, q1);
                A3 = packh2(q2, q3);
            }

            mma16816(acc2[0], A0, A1, A2, A3, v00, v01);
            mma16816(acc2[1], A0, A1, A2, A3, v02, v03);
            mma16816(acc2[2], A0, A1, A2, A3, v10, v11);
            mma16816(acc2[3], A0, A1, A2, A3, v12, v13);

            #pragma unroll
            for (int dc = 2; dc < 8; ++dc) {
                uint32_t w0, w1, w2, w3;
                ldsm_x4t(w0, w1, w2, w3, vrow + dc * 32);
                mma16816(acc2[2 * dc],     A0, A1, A2, A3, w0, w1);
                mma16816(acc2[2 * dc + 1], A0, A1, A2, A3, w2, w3);
            }
        }

        GBAR;                           // group done with V(it)/mask(it)
    }

    __syncthreads();

    // ---- r reduction ----
    float* sR = (float*)(smem + SM_R);
    #pragma unroll
    for (int half = 0; half < 2; ++half) {
        float vv = rsum[half];
        vv += __shfl_xor_sync(0xffffffffu, vv, 1);
        vv += __shfl_xor_sync(0xffffffffu, vv, 2);
        if (t == 0) sR[wn * BM + m_base + half * 8 + g] = vv;
    }

    // ---- O split-k reduction ----
    float* ost = (float*)(smem + SM_OST);
    if (wn == 0) {
        #pragma unroll
        for (int nt = 0; nt < 16; ++nt) {
            const int row0 = m_base + g;
            const int cb = nt * 8 + 2 * t;
            *(float2*)&ost[row0 * 136 + cb] = make_float2(acc2[nt][0], acc2[nt][1]);
            *(float2*)&ost[(row0 + 8) * 136 + cb] = make_float2(acc2[nt][2], acc2[nt][3]);
        }
    }
    __syncthreads();

    if (wn == 1) {
        float* ob = o + ((size_t)(b * HH + h) * SS + s0) * DH;
        const int row0 = m_base + g;
        const int row1 = row0 + 8;
        const float inv0 = 1.0f / fmaxf(sR[row0] + sR[BM + row0], 1.0f);
        const float inv1 = 1.0f / fmaxf(sR[row1] + sR[BM + row1], 1.0f);
        #pragma unroll
        for (int nt = 0; nt < 16; ++nt) {
            const int cb = nt * 8 + 2 * t;
            float2 s0v = *(const float2*)&ost[row0 * 136 + cb];
            float2 s1v = *(const float2*)&ost[row1 * 136 + cb];
            *(float2*)&ob[(size_t)row0 * DH + cb] =
                make_float2((s0v.x + acc2[nt][0]) * inv0, (s0v.y + acc2[nt][1]) * inv0);
            *(float2*)&ob[(size_t)row1 * DH + cb] =
                make_float2((s1v.x + acc2[nt][2]) * inv1, (s1v.y + acc2[nt][3]) * inv1);
        }
    }
}

extern "C" void kernel_launch(void* const* d_in, const int* in_sizes, int n_in,
                              void* d_out, int out_size) {
    const float* q = (const float*)d_in[0];
    const float* k = (const float*)d_in[1];
    const float* v = (const float*)d_in[2];
    const float* m = (const float*)d_in[3];
    float* o = (float*)d_out;
    conv_kv<<<(BB * HH * SS * DH / 4) / 512, 512>>>(k, v);
    cudaFuncSetAttribute(retatt_k16,
                         cudaFuncAttributeMaxDynamicSharedMemorySize, SMEM_BYTES);
    retatt_k16<<<BB * HH * NSTILE, NTHREADS, SMEM_BYTES>>>(q, m, o);
}

// round 17
// speedup vs baseline: 1.4501x; 1.1919x over previous
#include <cuda_runtime.h>
#include <cuda_fp16.h>
#include <cstdint>

#define BB 2
#define HH 16
#define SS 2048
#define DH 128
#define BM 128
#define BN 128
#define NITER 16
#define NSTILE 16
#define NTHREADS 512

// smem byte layout (r8/r11 — the measured-best configuration)
#define QSB 272              // Q/K/V row stride (17*16B, ldmatrix conflict-free)
#define KVST 34816           // one K/V stage: 128*272
#define MSKW 136             // mask row stride in words (544 B)
#define SM_Q 0               // 34816
#define SM_K 34816           // 2 stages -> 104448
#define SM_V 104448          // 1 stage  -> 139264
#define SM_M 139264          // 128*544 = 69632 -> 208896
#define SM_R 208896          // 2*128 floats
#define SM_OST SM_K          // O staging (post-loop)
#define SMEM_BYTES 209920

// fp16 K/V scratch, filled by conv_kv kernel
__device__ __half KH[BB * HH * SS * DH];
__device__ __half VH[BB * HH * SS * DH];

__device__ __forceinline__ uint32_t smem_u32(const void* p) {
    uint32_t a;
    asm("{ .reg .u64 t; cvta.to.shared.u64 t, %1; cvt.u32.u64 %0, t; }" : "=r"(a) : "l"(p));
    return a;
}
__device__ __forceinline__ void ldsm_x4(uint32_t& r0, uint32_t& r1, uint32_t& r2, uint32_t& r3, uint32_t a) {
    asm volatile("ldmatrix.sync.aligned.m8n8.x4.shared.b16 {%0,%1,%2,%3}, [%4];"
                 : "=r"(r0), "=r"(r1), "=r"(r2), "=r"(r3) : "r"(a));
}
__device__ __forceinline__ void ldsm_x4t(uint32_t& r0, uint32_t& r1, uint32_t& r2, uint32_t& r3, uint32_t a) {
    asm volatile("ldmatrix.sync.aligned.m8n8.x4.trans.shared.b16 {%0,%1,%2,%3}, [%4];"
                 : "=r"(r0), "=r"(r1), "=r"(r2), "=r"(r3) : "r"(a));
}
__device__ __forceinline__ void mma16816(float* c, uint32_t a0, uint32_t a1, uint32_t a2, uint32_t a3,
                                         uint32_t b0, uint32_t b1) {
    asm volatile(
        "mma.sync.aligned.m16n8k16.row.col.f32.f16.f16.f32 "
        "{%0,%1,%2,%3}, {%4,%5,%6,%7}, {%8,%9}, {%0,%1,%2,%3};"
        : "+f"(c[0]), "+f"(c[1]), "+f"(c[2]), "+f"(c[3])
        : "r"(a0), "r"(a1), "r"(a2), "r"(a3), "r"(b0), "r"(b1));
}
__device__ __forceinline__ void cpa16(uint32_t dst, const void* src) {
    asm volatile("cp.async.cg.shared.global [%0], [%1], 16;" :: "r"(dst), "l"(src) : "memory");
}
#define CPA_COMMIT asm volatile("cp.async.commit_group;" ::: "memory")
#define CPA_WAIT(n) asm volatile("cp.async.wait_group %0;" :: "n"(n) : "memory")
#define GBAR asm volatile("bar.sync %0, 256;" :: "r"(wn + 1) : "memory")

__device__ __forceinline__ uint2 f4h4(float4 v) {
    __half2 a = __floats2half2_rn(v.x, v.y);
    __half2 b = __floats2half2_rn(v.z, v.w);
    uint2 w;
    w.x = *(uint32_t*)&a;
    w.y = *(uint32_t*)&b;
    return w;
}
__device__ __forceinline__ uint32_t packh2(float a, float b) {
    __half2 h = __floats2half2_rn(a, b);
    return *(uint32_t*)&h;
}

__global__ __launch_bounds__(512, 2)
void conv_kv(const float* __restrict__ k, const float* __restrict__ v) {
    int i = blockIdx.x * blockDim.x + threadIdx.x;
    ((uint2*)KH)[i] = f4h4(((const float4*)k)[i]);
    ((uint2*)VH)[i] = f4h4(((const float4*)v)[i]);
}

__global__ __launch_bounds__(NTHREADS, 1)
void retatt_k17(const float* __restrict__ q, const float* __restrict__ mask,
                float* __restrict__ o)
{
    extern __shared__ char smem[];
    const uint32_t sbase = smem_u32(smem);
    const int tid = threadIdx.x;
    const int wid = tid >> 5;
    const int lane = tid & 31;
    const int g = lane >> 2;
    const int t = lane & 3;
    const int wm = wid >> 1;            // r8 mapping: 0..7 m-strip
    const int wn = wid & 1;             // r8 mapping: group per SMSP pair
    const int m_base = wm * 16;
    const int n_base = wn * 64;
    const int lrow = lane & 15;
    const int lchunk = (lane >> 4) * 16;
    const int gt = wm * 32 + lane;      // thread id within 256-thread group

    const int bid = blockIdx.x;
    const int b  = bid & 1;
    const int r_ = bid >> 1;
    const int h  = r_ / NSTILE;
    const int st = r_ % NSTILE;
    const int s0 = st * BM;

    const float* qbase = q + ((size_t)(b * HH + h) * SS + s0) * DH;
    const __half* khb = KH + ((size_t)(b * HH + h) * SS) * DH;
    const __half* vhb = VH + ((size_t)(b * HH + h) * SS) * DH;
    const float* mbase = mask + ((size_t)h * SS + s0) * SS;

    // ---- prologue: Q fp16; K0 group-half via cp.async ----
    {
        const float4* gq = (const float4*)qbase;
        #pragma unroll
        for (int i = 0; i < 8; ++i) {
            int f = tid + i * NTHREADS;
            int row = f >> 5, d = (f & 31) << 2;
            *(uint2*)(smem + SM_Q + row * QSB + d * 2) = f4h4(gq[f]);
        }
        #pragma unroll
        for (int i = 0; i < 4; ++i) {
            int f = gt + i * 256;
            int lr = f >> 4, c16 = f & 15;
            cpa16(sbase + SM_K + (n_base + lr) * QSB + c16 * 16,
                  khb + (size_t)(n_base + lr) * DH + c16 * 8);
        }
        CPA_COMMIT;
        __syncthreads();
    }

    float acc2[16][4];
    #pragma unroll
    for (int nt = 0; nt < 16; ++nt)
        #pragma unroll
        for (int i = 0; i < 4; ++i) acc2[nt][i] = 0.f;
    float rsum[2] = {0.f, 0.f};

    const uint32_t qa = sbase + SM_Q + (uint32_t)(m_base + lrow) * QSB + lchunk;
    const uint32_t sV = sbase + SM_V;

    #pragma unroll 1
    for (int it = 0; it < NITER; ++it) {
        const uint32_t sKb = sbase + SM_K + (it & 1) * KVST;

        // ---- group-owned cp.async: V(it) half, mask(it) cols, K(it+1) half ----
        {
            #pragma unroll
            for (int i = 0; i < 4; ++i) {
                int f = gt + i * 256;
                int lr = f >> 4, c16 = f & 15;
                cpa16(sV + (n_base + lr) * QSB + c16 * 16,
                      vhb + (size_t)(it * BN + n_base + lr) * DH + c16 * 8);
            }
            #pragma unroll
            for (int i = 0; i < 8; ++i) {
                int f = gt + i * 256;
                int row = f >> 4, c16 = f & 15;
                cpa16(sbase + SM_M + row * (MSKW * 4) + n_base * 4 + c16 * 16,
                      mbase + (size_t)row * SS + it * BN + n_base + c16 * 4);
            }
            if (it + 1 < NITER) {
                const uint32_t kd = sbase + SM_K + ((it + 1) & 1) * KVST;
                #pragma unroll
                for (int i = 0; i < 4; ++i) {
                    int f = gt + i * 256;
                    int lr = f >> 4, c16 = f & 15;
                    cpa16(kd + (n_base + lr) * QSB + c16 * 16,
                          khb + (size_t)((it + 1) * BN + n_base + lr) * DH + c16 * 8);
                }
            }
            CPA_COMMIT;
        }

        CPA_WAIT(1);                    // this group's K(it) complete
        if (it == 0) GBAR;

        // ---- GEMM1: S[16 x 64] per warp = Q @ K_slice^T ----
        float acc1[8][4];
        #pragma unroll
        for (int nt = 0; nt < 8; ++nt)
            #pragma unroll
            for (int i = 0; i < 4; ++i) acc1[nt][i] = 0.f;

        const uint32_t kb0 = sKb + (uint32_t)(n_base + lrow) * QSB + lchunk;
        #pragma unroll
        for (int kk = 0; kk < 8; ++kk) {
            uint32_t a0, a1, a2, a3;
            ldsm_x4(a0, a1, a2, a3, qa + kk * 32);
            #pragma unroll
            for (int j = 0; j < 4; ++j) {
                uint32_t b0, b1, b2, b3;
                ldsm_x4(b0, b1, b2, b3, kb0 + j * 16 * QSB + kk * 32);
                mma16816(acc1[2 * j],     a0, a1, a2, a3, b0, b2);
                mma16816(acc1[2 * j + 1], a0, a1, a2, a3, b1, b3);
            }
        }

        CPA_WAIT(0);                    // this group's V(it), mask(it) complete
        GBAR;                           // group-wide visibility of V/mask

        // ---- FUSED epilogue + GEMM2 per k-block (the r11 win) ----
        const uint32_t moff = SM_M + (uint32_t)(m_base + g) * (MSKW * 4)
                            + (uint32_t)(n_base + 2 * t) * 4;
        #pragma unroll
        for (int kb = 0; kb < 4; ++kb) {
            const uint32_t vrow = sV + (uint32_t)(n_base + kb * 16 + lrow) * QSB + lchunk;

            // pre-issue V fragments for dc=0,1 (independent of epilogue ALU)
            uint32_t v00, v01, v02, v03, v10, v11, v12, v13;
            ldsm_x4t(v00, v01, v02, v03, vrow);
            ldsm_x4t(v10, v11, v12, v13, vrow + 32);

            uint32_t A0, A1, A2, A3;
            {
                const int nt0 = 2 * kb;
                float2 m0 = *(const float2*)(smem + moff + nt0 * 32);
                float2 m1 = *(const float2*)(smem + moff + 8 * (MSKW * 4) + nt0 * 32);
                float p0 = acc1[nt0][0] * m0.x;
                float p1 = acc1[nt0][1] * m0.y;
                float p2 = acc1[nt0][2] * m1.x;
                float p3 = acc1[nt0][3] * m1.y;
                rsum[0] += fabsf(p0) + fabsf(p1);
                rsum[1] += fabsf(p2) + fabsf(p3);
                A0 = packh2(p0, p1);
                A1 = packh2(p2, p3);

                const int nt1 = nt0 + 1;
                float2 m2 = *(const float2*)(smem + moff + nt1 * 32);
                float2 m3 = *(const float2*)(smem + moff + 8 * (MSKW * 4) + nt1 * 32);
                float q0 = acc1[nt1][0] * m2.x;
                float q1 = acc1[nt1][1] * m2.y;
                float q2 = acc1[nt1][2] * m3.x;
                float q3 = acc1[nt1][3] * m3.y;
                rsum[0] += fabsf(q0) + fabsf(q1);
                rsum[1] += fabsf(q2) + fabsf(q3);
                A2 = packh2(q0, q1);
                A3 = packh2(q2, q3);
            }

            mma16816(acc2[0], A0, A1, A2, A3, v00, v01);
            mma16816(acc2[1], A0, A1, A2, A3, v02, v03);
            mma16816(acc2[2], A0, A1, A2, A3, v10, v11);
            mma16816(acc2[3], A0, A1, A2, A3, v12, v13);

            #pragma unroll
            for (int dc = 2; dc < 8; ++dc) {
                uint32_t w0, w1, w2, w3;
                ldsm_x4t(w0, w1, w2, w3, vrow + dc * 32);
                mma16816(acc2[2 * dc],     A0, A1, A2, A3, w0, w1);
                mma16816(acc2[2 * dc + 1], A0, A1, A2, A3, w2, w3);
            }
        }

        GBAR;                           // group done with V(it)/mask(it)
    }

    __syncthreads();

    // ---- r reduction ----
    float* sR = (float*)(smem + SM_R);
    #pragma unroll
    for (int half = 0; half < 2; ++half) {
        float vv = rsum[half];
        vv += __shfl_xor_sync(0xffffffffu, vv, 1);
        vv += __shfl_xor_sync(0xffffffffu, vv, 2);
        if (t == 0) sR[wn * BM + m_base + half * 8 + g] = vv;
    }

    // ---- O split-k reduction ----
    float* ost = (float*)(smem + SM_OST);
    if (wn == 0) {
        #pragma unroll
        for (int nt = 0; nt < 16; ++nt) {
            const int row0 = m_base + g;
            const int cb = nt * 8 + 2 * t;
            *(float2*)&ost[row0 * 136 + cb] = make_float2(acc2[nt][0], acc2[nt][1]);
            *(float2*)&ost[(row0 + 8) * 136 + cb] = make_float2(acc2[nt][2], acc2[nt][3]);
        }
    }
    __syncthreads();

    if (wn == 1) {
        float* ob = o + ((size_t)(b * HH + h) * SS + s0) * DH;
        const int row0 = m_base + g;
        const int row1 = row0 + 8;
        const float inv0 = 1.0f / fmaxf(sR[row0] + sR[BM + row0], 1.0f);
        const float inv1 = 1.0f / fmaxf(sR[row1] + sR[BM + row1], 1.0f);
        #pragma unroll
        for (int nt = 0; nt < 16; ++nt) {
            const int cb = nt * 8 + 2 * t;
            float2 s0v = *(const float2*)&ost[row0 * 136 + cb];
            float2 s1v = *(const float2*)&ost[row1 * 136 + cb];
            *(float2*)&ob[(size_t)row0 * DH + cb] =
                make_float2((s0v.x + acc2[nt][0]) * inv0, (s0v.y + acc2[nt][1]) * inv0);
            *(float2*)&ob[(size_t)row1 * DH + cb] =
                make_float2((s1v.x + acc2[nt][2]) * inv1, (s1v.y + acc2[nt][3]) * inv1);
        }
    }
}

extern "C" void kernel_launch(void* const* d_in, const int* in_sizes, int n_in,
                              void* d_out, int out_size) {
    const float* q = (const float*)d_in[0];
    const float* k = (const float*)d_in[1];
    const float* v = (const float*)d_in[2];
    const float* m = (const float*)d_in[3];
    float* o = (float*)d_out;
    conv_kv<<<(BB * HH * SS * DH / 4) / 512, 512>>>(k, v);
    cudaFuncSetAttribute(retatt_k17,
                         cudaFuncAttributeMaxDynamicSharedMemorySize, SMEM_BYTES);
    retatt_k17<<<BB * HH * NSTILE, NTHREADS, SMEM_BYTES>>>(q, m, o);
}